// round 4
// baseline (speedup 1.0000x reference)
#include <cuda_runtime.h>
#include <math.h>
#include <stdint.h>

#define NUM_BINS 16
#define DIM      512
#define IN_DIM   768
#define NTOK     2048
#define HALFD    256
#define MT       128       // CTA tile M
#define NT       128       // CTA tile F
#define KT       32        // K tile
#define RP       36        // smem row pitch in floats (32 + 4 pad)
#define NTILES   (IN_DIM / KT)   // 24

// -------- device scratch (no allocations allowed) --------
__device__ float g_cos[NTOK * HALFD];
__device__ float g_sin[NTOK * HALFD];
__device__ float g_w[DIM * NUM_BINS];

// -------- setup: RoPE cos/sin table --------
__global__ void rope_table_kernel(const int* __restrict__ offset_p) {
    int idx = blockIdx.x * blockDim.x + threadIdx.x;
    if (idx >= NTOK * HALFD) return;
    int n = idx >> 8;          // / 256
    int j = idx & 255;
    float half  = (float)j * (1.0f / 256.0f);
    // 10000^-h = 2^(-h*log2(1e4)),  100000^-h = 2^(-h*log2(1e5))
    float inv_h = exp2f(-half * 13.287712379549449f);
    float inv_d = exp2f(-half * 16.609640474436812f);
    int off = offset_p ? offset_p[0] : 0;
    float fi    = (float)(n + off);
    float days  = floorf(fi * (1.0f / 64.0f));
    float hours = fi - days * 64.0f;
    float ang = hours * inv_h + days * inv_d;
    float s, c;
    sincosf(ang, &s, &c);
    g_cos[idx] = c;
    g_sin[idx] = s;
}

// -------- setup: w = softplus(spline_heights) --------
__global__ void softplus_kernel(const float* __restrict__ h) {
    int i = blockIdx.x * blockDim.x + threadIdx.x;
    if (i < DIM * NUM_BINS) {
        float v = h[i];
        g_w[i] = (v > 20.0f) ? v : log1pf(expf(v));
    }
}

// -------- helpers --------
__device__ __forceinline__ uint32_t smem_u32(const void* p) {
    return (uint32_t)__cvta_generic_to_shared(p);
}

__device__ __forceinline__ void cp16(uint32_t dst, const void* src) {
    asm volatile("cp.async.cg.shared.global [%0], [%1], 16;\n" :: "r"(dst), "l"(src));
}

__device__ __forceinline__ void ldsm4(uint32_t* r, uint32_t addr) {
    asm volatile("ldmatrix.sync.aligned.m8n8.x4.shared.b16 {%0,%1,%2,%3}, [%4];\n"
                 : "=r"(r[0]), "=r"(r[1]), "=r"(r[2]), "=r"(r[3]) : "r"(addr));
}

__device__ __forceinline__ void mma_tf32(float* c, const uint32_t* a, uint32_t b0, uint32_t b1) {
    asm volatile(
        "mma.sync.aligned.m16n8k8.row.col.f32.tf32.tf32.f32 "
        "{%0,%1,%2,%3}, {%4,%5,%6,%7}, {%8,%9}, {%0,%1,%2,%3};\n"
        : "+f"(c[0]), "+f"(c[1]), "+f"(c[2]), "+f"(c[3])
        : "r"(a[0]), "r"(a[1]), "r"(a[2]), "r"(a[3]), "r"(b0), "r"(b1));
}

// -------- fused tf32-MMA GEMM + sin/sigmoid/spline + RoPE --------
// grid (M/128, 512/128) = (128, 4); 256 threads = 8 warps in a 4x2 (m x f) grid.
// Each warp owns a 32(m) x 64(f) output tile: 2 m16-frags x 8 n8-frags.
__global__ __launch_bounds__(256, 2)
void fused_mma(const float* __restrict__ x,
               const float* __restrict__ freqs,
               const float* __restrict__ phase,
               const float* __restrict__ bias,
               float* __restrict__ out) {
    extern __shared__ float smem[];
    float* sA   = smem;                       // 2 * 128 * 36
    float* sB   = smem + 2 * MT * RP;         // 2 * 128 * 36
    float* s_w  = smem + 4 * MT * RP;         // 128 * 16
    float* s_ph = s_w + NT * NUM_BINS;        // 128
    float* s_bi = s_ph + NT;                  // 128

    const int tid  = threadIdx.x;
    const int lane = tid & 31;
    const int wid  = tid >> 5;
    const int warp_m = wid & 3;               // 0..3  -> 32-row slab
    const int warp_n = wid >> 2;              // 0..1  -> 64-col slab
    const int m0 = blockIdx.x * MT;
    const int f0 = blockIdx.y * NT;

    // stage per-f epilogue params
    for (int i = tid; i < NT * NUM_BINS; i += 256) s_w[i] = g_w[f0 * NUM_BINS + i];
    if (tid < NT) { s_ph[tid] = phase[f0 + tid]; s_bi[tid] = bias[f0 + tid]; }

    const uint32_t saA = smem_u32(sA);
    const uint32_t saB = smem_u32(sB);
    const int lrow = tid >> 3;   // 0..31 base (x8 float4 per row)
    const int lq   = tid & 7;

    // double-buffered async loads: 8 x cp.async(16B) per thread per tile
    auto issue_tile = [&](int t) {
        int k0 = t * KT;
        int buf = t & 1;
        uint32_t dA = saA + (uint32_t)(buf * MT * RP) * 4u;
        uint32_t dB = saB + (uint32_t)(buf * MT * RP) * 4u;
#pragma unroll
        for (int i = 0; i < 4; i++) {
            int row = lrow + i * 32;
            cp16(dA + (uint32_t)(row * RP + lq * 4) * 4u,
                 x + (size_t)(m0 + row) * IN_DIM + k0 + lq * 4);
            cp16(dB + (uint32_t)(row * RP + lq * 4) * 4u,
                 freqs + (size_t)(f0 + row) * IN_DIM + k0 + lq * 4);
        }
        asm volatile("cp.async.commit_group;\n" ::: "memory");
    };

    float acc[2][8][4];
#pragma unroll
    for (int i = 0; i < 2; i++)
#pragma unroll
        for (int j = 0; j < 8; j++)
#pragma unroll
            for (int k = 0; k < 4; k++) acc[i][j][k] = 0.0f;

    // ldmatrix per-thread address offsets (bytes)
    const int sel = lane >> 3, rin = lane & 7;
    const uint32_t a_off = (uint32_t)(((sel & 1) * 8 + rin) * RP + (sel >> 1) * 4) * 4u;
    const uint32_t b_off = (uint32_t)(((sel >> 1) * 8 + rin) * RP + (sel & 1) * 4) * 4u;

    issue_tile(0);
    for (int t = 0; t < NTILES; t++) {
        if (t + 1 < NTILES) {
            issue_tile(t + 1);
            asm volatile("cp.async.wait_group 1;\n" ::: "memory");
        } else {
            asm volatile("cp.async.wait_group 0;\n" ::: "memory");
        }
        __syncthreads();

        int buf = t & 1;
        uint32_t baseA = saA + (uint32_t)(buf * MT * RP + warp_m * 32 * RP) * 4u;
        uint32_t baseB = saB + (uint32_t)(buf * MT * RP + warp_n * 64 * RP) * 4u;
#pragma unroll
        for (int kk = 0; kk < 4; kk++) {
            uint32_t kb = (uint32_t)(kk * 8) * 4u;
            uint32_t a[2][4];
            ldsm4(a[0], baseA + a_off + kb);
            ldsm4(a[1], baseA + a_off + kb + (uint32_t)(16 * RP) * 4u);
            uint32_t b[4][4];   // pair p covers n-frags 2p (regs 0,1) and 2p+1 (regs 2,3)
#pragma unroll
            for (int p = 0; p < 4; p++)
                ldsm4(b[p], baseB + b_off + kb + (uint32_t)(p * 16 * RP) * 4u);
#pragma unroll
            for (int mf = 0; mf < 2; mf++)
#pragma unroll
                for (int p = 0; p < 4; p++) {
                    mma_tf32(acc[mf][2 * p],     a[mf], b[p][0], b[p][1]);
                    mma_tf32(acc[mf][2 * p + 1], a[mf], b[p][2], b[p][3]);
                }
        }
        __syncthreads();
    }

    // ------- epilogue: sin -> sigmoid -> spline -> rope -------
    // C frag: c0=(g,2t) c1=(g,2t+1) c2=(g+8,2t) c3=(g+8,2t+1) => rope pair in-thread
    const int t4 = lane & 3, g = lane >> 2;
#pragma unroll
    for (int nf = 0; nf < 8; nf++) {
        int fl = warp_n * 64 + nf * 8 + 2 * t4;   // local even f
        int fp = f0 + fl;
        float ph0 = s_ph[fl], ph1 = s_ph[fl + 1];
        float bi0 = s_bi[fl], bi1 = s_bi[fl + 1];
        const float* w0 = s_w + fl * NUM_BINS;
        const float* w1 = w0 + NUM_BINS;
        int j = fp >> 1;
#pragma unroll
        for (int mf = 0; mf < 2; mf++) {
            int rbase = m0 + warp_m * 32 + mf * 16 + g;
#pragma unroll
            for (int h = 0; h < 2; h++) {
                int r = rbase + h * 8;
                float z0 = acc[mf][nf][2 * h + 0] + ph0;
                float z1 = acc[mf][nf][2 * h + 1] + ph1;
                float b0 = sinf(z0), b1 = sinf(z1);
                float u0 = 1.0f / (1.0f + expf(-b0));
                float u1 = 1.0f / (1.0f + expf(-b1));
                float v0 = bi0, v1 = bi1;
#pragma unroll
                for (int k = 0; k < NUM_BINS; k++) {
                    float gk = (float)k * (1.0f / 15.0f);
                    v0 += w0[k] * fmaxf(u0 - gk, 0.0f);
                    v1 += w1[k] * fmaxf(u1 - gk, 0.0f);
                }
                int n = r & (NTOK - 1);
                float cs = g_cos[n * HALFD + j];
                float sn = g_sin[n * HALFD + j];
                float2 o;
                o.x = v0 * cs - v1 * sn;
                o.y = v0 * sn + v1 * cs;
                *(float2*)&out[(size_t)r * DIM + fp] = o;
            }
        }
    }
}

#define SMEM_BYTES ((4 * MT * RP + NT * NUM_BINS + 2 * NT) * 4)

extern "C" void kernel_launch(void* const* d_in, const int* in_sizes, int n_in,
                              void* d_out, int out_size) {
    const float* x       = (const float*)d_in[0];   // (8,2048,768)
    const float* freqs   = (const float*)d_in[1];   // (512,768)
    const float* phase   = (const float*)d_in[2];   // (512,1)
    const float* heights = (const float*)d_in[3];   // (512,16)
    const float* bias    = (const float*)d_in[4];   // (512,)
    const int*   offset  = (n_in > 5) ? (const int*)d_in[5] : nullptr;
    float* out = (float*)d_out;                     // (8,2048,512) f32

    cudaFuncSetAttribute(fused_mma, cudaFuncAttributeMaxDynamicSharedMemorySize, SMEM_BYTES);

    rope_table_kernel<<<(NTOK * HALFD + 255) / 256, 256>>>(offset);
    softplus_kernel<<<(DIM * NUM_BINS + 255) / 256, 256>>>(heights);

    dim3 grid((8 * NTOK) / MT, DIM / NT);           // (128, 4)
    fused_mma<<<grid, 256, SMEM_BYTES>>>(x, freqs, phase, bias, out);
}

// round 14
// speedup vs baseline: 1.5960x; 1.5960x over previous
#include <cuda_runtime.h>
#include <math.h>
#include <stdint.h>

#define NUM_BINS 16
#define DIM      512
#define IN_DIM   768
#define NTOK     2048
#define HALFD    256
#define MT       128       // CTA tile M
#define NT       128       // CTA tile F
#define KT       32        // K tile
#define RP       36        // smem row pitch in floats (32 + 4 pad)
#define NTILES   (IN_DIM / KT)   // 24

// -------- device scratch (no allocations allowed) --------
__device__ float  g_cos[NTOK * HALFD];
__device__ float  g_sin[NTOK * HALFD];
__device__ float2 g_sp[DIM * NUM_BINS];   // (slope S_j, intercept I_j) incl. bias

// -------- merged setup: RoPE table + piecewise-linear spline LUT --------
// val(u) = bias + sum_{k<=j} w_k*(u - g_k)  for u in [g_j, g_{j+1})
//        = S_j*u + I_j,  S_j = prefix_sum(w), I_j = bias - prefix_sum(w*g)
__global__ void setup_kernel(const int* __restrict__ offset_p,
                             const float* __restrict__ heights,
                             const float* __restrict__ bias) {
    int idx = blockIdx.x * blockDim.x + threadIdx.x;
    if (idx < DIM) {
        float S = 0.0f, I = bias[idx];
        const float* h = heights + idx * NUM_BINS;
        float2* sp = g_sp + idx * NUM_BINS;
#pragma unroll
        for (int k = 0; k < NUM_BINS; k++) {
            float v = h[k];
            float w = (v > 20.0f) ? v : log1pf(expf(v));
            S += w;
            I -= w * ((float)k * (1.0f / 15.0f));
            sp[k] = make_float2(S, I);
        }
    }
    if (idx >= NTOK * HALFD) return;
    int n = idx >> 8;
    int j = idx & 255;
    float half  = (float)j * (1.0f / 256.0f);
    float inv_h = exp2f(-half * 13.287712379549449f);   // 10000^-half
    float inv_d = exp2f(-half * 16.609640474436812f);   // 100000^-half
    float fi    = (float)(n + offset_p[0]);
    float days  = floorf(fi * (1.0f / 64.0f));
    float hours = fi - days * 64.0f;
    float ang = hours * inv_h + days * inv_d;
    float s, c;
    sincosf(ang, &s, &c);
    g_cos[idx] = c;
    g_sin[idx] = s;
}

// -------- helpers --------
__device__ __forceinline__ uint32_t smem_u32(const void* p) {
    return (uint32_t)__cvta_generic_to_shared(p);
}

__device__ __forceinline__ void cp16(uint32_t dst, const void* src) {
    asm volatile("cp.async.cg.shared.global [%0], [%1], 16;\n" :: "r"(dst), "l"(src));
}

__device__ __forceinline__ void ldsm4(uint32_t* r, uint32_t addr) {
    asm volatile("ldmatrix.sync.aligned.m8n8.x4.shared.b16 {%0,%1,%2,%3}, [%4];\n"
                 : "=r"(r[0]), "=r"(r[1]), "=r"(r[2]), "=r"(r[3]) : "r"(addr));
}

__device__ __forceinline__ void mma_tf32(float* c, const uint32_t* a, uint32_t b0, uint32_t b1) {
    asm volatile(
        "mma.sync.aligned.m16n8k8.row.col.f32.tf32.tf32.f32 "
        "{%0,%1,%2,%3}, {%4,%5,%6,%7}, {%8,%9}, {%0,%1,%2,%3};\n"
        : "+f"(c[0]), "+f"(c[1]), "+f"(c[2]), "+f"(c[3])
        : "r"(a[0]), "r"(a[1]), "r"(a[2]), "r"(a[3]), "r"(b0), "r"(b1));
}

// -------- fused tf32-MMA GEMM + sin/sigmoid/spline(PWL) + RoPE --------
__global__ __launch_bounds__(256, 2)
void fused_mma(const float* __restrict__ x,
               const float* __restrict__ freqs,
               const float* __restrict__ phase,
               float* __restrict__ out) {
    extern __shared__ float smem[];
    float*  sA   = smem;                        // 2 * 128 * 36
    float*  sB   = smem + 2 * MT * RP;          // 2 * 128 * 36
    float2* s_sp = (float2*)(smem + 4 * MT * RP);   // 128 * 16 float2
    float*  s_ph = (float*)(s_sp + NT * NUM_BINS);  // 128

    const int tid  = threadIdx.x;
    const int lane = tid & 31;
    const int wid  = tid >> 5;
    const int warp_m = wid & 3;
    const int warp_n = wid >> 2;
    const int m0 = blockIdx.x * MT;
    const int f0 = blockIdx.y * NT;

    // stage per-f epilogue params
    for (int i = tid; i < NT * NUM_BINS; i += 256) s_sp[i] = g_sp[f0 * NUM_BINS + i];
    if (tid < NT) s_ph[tid] = phase[f0 + tid];

    const uint32_t saA = smem_u32(sA);
    const uint32_t saB = smem_u32(sB);
    const int lrow = tid >> 3;
    const int lq   = tid & 7;

    auto issue_tile = [&](int t) {
        int k0 = t * KT;
        int buf = t & 1;
        uint32_t dA = saA + (uint32_t)(buf * MT * RP) * 4u;
        uint32_t dB = saB + (uint32_t)(buf * MT * RP) * 4u;
#pragma unroll
        for (int i = 0; i < 4; i++) {
            int row = lrow + i * 32;
            cp16(dA + (uint32_t)(row * RP + lq * 4) * 4u,
                 x + (size_t)(m0 + row) * IN_DIM + k0 + lq * 4);
            cp16(dB + (uint32_t)(row * RP + lq * 4) * 4u,
                 freqs + (size_t)(f0 + row) * IN_DIM + k0 + lq * 4);
        }
        asm volatile("cp.async.commit_group;\n" ::: "memory");
    };

    float acc[2][8][4];
#pragma unroll
    for (int i = 0; i < 2; i++)
#pragma unroll
        for (int j = 0; j < 8; j++)
#pragma unroll
            for (int k = 0; k < 4; k++) acc[i][j][k] = 0.0f;

    const int sel = lane >> 3, rin = lane & 7;
    const uint32_t a_off = (uint32_t)(((sel & 1) * 8 + rin) * RP + (sel >> 1) * 4) * 4u;
    const uint32_t b_off = (uint32_t)(((sel >> 1) * 8 + rin) * RP + (sel & 1) * 4) * 4u;

    issue_tile(0);
    for (int t = 0; t < NTILES; t++) {
        if (t + 1 < NTILES) {
            issue_tile(t + 1);
            asm volatile("cp.async.wait_group 1;\n" ::: "memory");
        } else {
            asm volatile("cp.async.wait_group 0;\n" ::: "memory");
        }
        __syncthreads();

        int buf = t & 1;
        uint32_t baseA = saA + (uint32_t)(buf * MT * RP + warp_m * 32 * RP) * 4u;
        uint32_t baseB = saB + (uint32_t)(buf * MT * RP + warp_n * 64 * RP) * 4u;
#pragma unroll
        for (int kk = 0; kk < 4; kk++) {
            uint32_t kb = (uint32_t)(kk * 8) * 4u;
            uint32_t a[2][4];
            ldsm4(a[0], baseA + a_off + kb);
            ldsm4(a[1], baseA + a_off + kb + (uint32_t)(16 * RP) * 4u);
            uint32_t b[4][4];
#pragma unroll
            for (int p = 0; p < 4; p++)
                ldsm4(b[p], baseB + b_off + kb + (uint32_t)(p * 16 * RP) * 4u);
#pragma unroll
            for (int mf = 0; mf < 2; mf++)
#pragma unroll
                for (int p = 0; p < 4; p++) {
                    mma_tf32(acc[mf][2 * p],     a[mf], b[p][0], b[p][1]);
                    mma_tf32(acc[mf][2 * p + 1], a[mf], b[p][2], b[p][3]);
                }
        }
        __syncthreads();
    }

    // ------- epilogue: sin -> sigmoid -> PWL spline -> rope -------
    const int t4 = lane & 3, g = lane >> 2;
#pragma unroll
    for (int nf = 0; nf < 8; nf++) {
        int fl = warp_n * 64 + nf * 8 + 2 * t4;
        int fp = f0 + fl;
        float ph0 = s_ph[fl], ph1 = s_ph[fl + 1];
        const float2* sp0 = s_sp + fl * NUM_BINS;
        const float2* sp1 = sp0 + NUM_BINS;
        int j = fp >> 1;
#pragma unroll
        for (int mf = 0; mf < 2; mf++) {
            int rbase = m0 + warp_m * 32 + mf * 16 + g;
#pragma unroll
            for (int h = 0; h < 2; h++) {
                int r = rbase + h * 8;
                float b0 = __sinf(acc[mf][nf][2 * h + 0] + ph0);
                float b1 = __sinf(acc[mf][nf][2 * h + 1] + ph1);
                float u0 = __fdividef(1.0f, 1.0f + __expf(-b0));
                float u1 = __fdividef(1.0f, 1.0f + __expf(-b1));
                int j0 = min((int)(u0 * 15.0f), 15);
                int j1 = min((int)(u1 * 15.0f), 15);
                float2 si0 = sp0[j0];
                float2 si1 = sp1[j1];
                float v0 = fmaf(si0.x, u0, si0.y);
                float v1 = fmaf(si1.x, u1, si1.y);
                int n = r & (NTOK - 1);
                float cs = g_cos[n * HALFD + j];
                float sn = g_sin[n * HALFD + j];
                float2 o;
                o.x = v0 * cs - v1 * sn;
                o.y = v0 * sn + v1 * cs;
                *(float2*)&out[(size_t)r * DIM + fp] = o;
            }
        }
    }
}

#define SMEM_BYTES ((4 * MT * RP) * 4 + (NT * NUM_BINS) * 8 + NT * 4)

extern "C" void kernel_launch(void* const* d_in, const int* in_sizes, int n_in,
                              void* d_out, int out_size) {
    const float* x       = (const float*)d_in[0];   // (8,2048,768)
    const float* freqs   = (const float*)d_in[1];   // (512,768)
    const float* phase   = (const float*)d_in[2];   // (512,1)
    const float* heights = (const float*)d_in[3];   // (512,16)
    const float* bias    = (const float*)d_in[4];   // (512,)
    const int*   offset  = (const int*)d_in[5];     // scalar
    float* out = (float*)d_out;                     // (8,2048,512) f32

    cudaFuncSetAttribute(fused_mma, cudaFuncAttributeMaxDynamicSharedMemorySize, SMEM_BYTES);

    setup_kernel<<<(NTOK * HALFD + 255) / 256, 256>>>(offset, heights, bias);

    dim3 grid((8 * NTOK) / MT, DIM / NT);           // (128, 4)
    fused_mma<<<grid, 256, SMEM_BYTES>>>(x, freqs, phase, out);
}